// round 1
// baseline (speedup 1.0000x reference)
#include <cuda_runtime.h>
#include <math.h>

#define HWTOK 50176          // 224*224
#define BATCH 8
#define NPARAM 4576
#define KP 17                // 11 taps + 3 guard zeros each side

// packed per-batch layout (floats)
#define OFF_CW1 0            // 3*16*17  = 816
#define OFF_CW2 816          // 16*16*17 = 4352
#define OFF_CW3 5168         // 16*3*17  = 816
#define OFF_RW1 5984         // 48
#define OFF_RW2 6032         // 256
#define OFF_RW3 6288         // 48
#define PACKED_PER_B 6336

__device__ float g_w[BATCH * NPARAM];
__device__ float g_packed[BATCH * PACKED_PER_B];

// ---------------------------------------------------------------------------
// Kernel 1: w[b][p] = features[b,:] . fc_w[p,:] + fc_b[p]
// One warp per p, all 8 batches simultaneously (fc_w read once).
// ---------------------------------------------------------------------------
__global__ void compute_w_kernel(const float* __restrict__ features,
                                 const float* __restrict__ fc_w,
                                 const float* __restrict__ fc_b)
{
    __shared__ float sfeat[BATCH * 1000];
    for (int idx = threadIdx.x; idx < BATCH * 1000; idx += blockDim.x)
        sfeat[idx] = features[idx];
    __syncthreads();

    int warp = (blockIdx.x * blockDim.x + threadIdx.x) >> 5;
    int lane = threadIdx.x & 31;
    if (warp >= NPARAM) return;

    const float* row = fc_w + warp * 1000;
    float acc[BATCH];
#pragma unroll
    for (int b = 0; b < BATCH; b++) acc[b] = 0.0f;

    for (int c = lane; c < 1000; c += 32) {
        float fw = row[c];
#pragma unroll
        for (int b = 0; b < BATCH; b++)
            acc[b] = fmaf(fw, sfeat[b * 1000 + c], acc[b]);
    }
#pragma unroll
    for (int b = 0; b < BATCH; b++) {
#pragma unroll
        for (int off = 16; off; off >>= 1)
            acc[b] += __shfl_xor_sync(0xffffffffu, acc[b], off);
    }
    if (lane == 0) {
        float bb = fc_b[warp];
#pragma unroll
        for (int b = 0; b < BATCH; b++)
            g_w[b * NPARAM + warp] = acc[b] + bb;
    }
}

// ---------------------------------------------------------------------------
// Kernel 2: build fused, padded per-batch parameter block:
//   cw[i][o][k(+3)] = coef[i][o][k] * uw[i][o]   (zeros in guard region)
//   rw[i][o]
// ---------------------------------------------------------------------------
__global__ void pack_kernel()
{
    int b = blockIdx.x;
    const float* w = g_w + b * NPARAM;
    float* pk = g_packed + b * PACKED_PER_B;

    for (int idx = threadIdx.x; idx < PACKED_PER_B; idx += blockDim.x)
        pk[idx] = 0.0f;
    __syncthreads();

    const int i0s[3]   = {0,    624,  3952};
    const int i1s[3]   = {528,  3440, 4480};
    const int i2s[3]   = {576,  3696, 4528};
    const int dis[3]   = {3, 16, 16};
    const int dos[3]   = {16, 16, 3};
    const int cwoff[3] = {OFF_CW1, OFF_CW2, OFF_CW3};
    const int rwoff[3] = {OFF_RW1, OFF_RW2, OFF_RW3};

    for (int n = 0; n < 3; n++) {
        int nd = dis[n] * dos[n];
        for (int p = threadIdx.x; p < nd; p += blockDim.x) {
            float uwv = w[i1s[n] + p];
            const float* cf = w + i0s[n] + p * 11;
            float* dst = pk + cwoff[n] + p * KP + 3;
#pragma unroll
            for (int k = 0; k < 11; k++) dst[k] = cf[k] * uwv;
            pk[rwoff[n] + p] = w[i2s[n] + p];
        }
    }
}

// ---------------------------------------------------------------------------
// Main kernel: one thread = one token; 3 KAN layers with closed-form
// uniform cubic B-spline (4 nonzero taps, gathered from smem).
// ---------------------------------------------------------------------------
__device__ __forceinline__ void bweights(float v, int& j,
                                         float& w0, float& w1, float& w2, float& w3)
{
    float x4 = (v + 1.75f) * 4.0f;
    float jf = floorf(x4);
    bool inr = (x4 >= 0.0f) && (x4 < 14.0f);
    j = inr ? (int)jf : 0;
    float t  = x4 - jf;
    float u  = 1.0f - t;
    float t2 = t * t;
    float t3 = t2 * t;
    w0 = u * u * u * (1.0f / 6.0f);          // N_{j-3}
    w1 = 0.5f * t3 - t2 + (2.0f / 3.0f);     // N_{j-2}
    w3 = t3 * (1.0f / 6.0f);                 // N_j
    w2 = 1.0f - w0 - w1 - w3;                // N_{j-1} (partition of unity)
    if (!inr) { w0 = w1 = w2 = w3 = 0.0f; }
}

template<int DI, int DO>
__device__ __forceinline__ void kan_layer(const float* __restrict__ cw,
                                          const float* __restrict__ rw,
                                          const float* __restrict__ in,
                                          float* __restrict__ outv)
{
#pragma unroll
    for (int o = 0; o < DO; o++) outv[o] = 0.0f;

#pragma unroll
    for (int i = 0; i < DI; i++) {
        float v = in[i];
        int j; float w0, w1, w2, w3;
        bweights(v, j, w0, w1, w2, w3);
        float sl = v / (1.0f + __expf(-v));   // silu

        const float* row = cw + i * (DO * KP) + j;

        float rwr[DO];
        if (DO % 4 == 0) {
#pragma unroll
            for (int o4 = 0; o4 < DO; o4 += 4) {
                float4 rv = *reinterpret_cast<const float4*>(rw + i * DO + o4);
                rwr[o4] = rv.x; rwr[o4 + 1] = rv.y; rwr[o4 + 2] = rv.z; rwr[o4 + 3] = rv.w;
            }
        } else {
#pragma unroll
            for (int o = 0; o < DO; o++) rwr[o] = rw[i * DO + o];
        }

#pragma unroll
        for (int o = 0; o < DO; o++) {
            const float* r = row + o * KP;
            float s = fmaf(w0, r[0], fmaf(w1, r[1], fmaf(w2, r[2], w3 * r[3])));
            outv[o] += fmaf(sl, rwr[o], s);
        }
    }
}

__global__ void __launch_bounds__(256, 2)
kan_main_kernel(const float* __restrict__ x, float* __restrict__ out)
{
    __shared__ __align__(16) float sp[PACKED_PER_B];
    int b = blockIdx.y;
    const float* src = g_packed + b * PACKED_PER_B;
    for (int idx = threadIdx.x; idx < PACKED_PER_B; idx += blockDim.x)
        sp[idx] = src[idx];
    __syncthreads();

    int t = blockIdx.x * blockDim.x + threadIdx.x;
    const float* xb = x + b * (3 * HWTOK);

    float in1[3];
    in1[0] = xb[t];
    in1[1] = xb[HWTOK + t];
    in1[2] = xb[2 * HWTOK + t];

    float h1[16], h2[16], h3[3];
    kan_layer<3, 16>(sp + OFF_CW1, sp + OFF_RW1, in1, h1);
    kan_layer<16, 16>(sp + OFF_CW2, sp + OFF_RW2, h1, h2);
    kan_layer<16, 3>(sp + OFF_CW3, sp + OFF_RW3, h2, h3);

    float* ob = out + b * (3 * HWTOK);
    ob[t]             = h3[0];
    ob[HWTOK + t]     = h3[1];
    ob[2 * HWTOK + t] = h3[2];
}

// ---------------------------------------------------------------------------
extern "C" void kernel_launch(void* const* d_in, const int* in_sizes, int n_in,
                              void* d_out, int out_size)
{
    const float* x   = (const float*)d_in[0];
    const float* ft  = (const float*)d_in[1];
    const float* fcw = (const float*)d_in[2];
    const float* fcb = (const float*)d_in[3];
    float* out = (float*)d_out;

    compute_w_kernel<<<(NPARAM * 32 + 255) / 256, 256>>>(ft, fcw, fcb);
    pack_kernel<<<BATCH, 256>>>();
    dim3 g(HWTOK / 256, BATCH);
    kan_main_kernel<<<g, 256>>>(x, out);
}